// round 1
// baseline (speedup 1.0000x reference)
#include <cuda_runtime.h>
#include <math.h>

// Problem constants
constexpr int N_B   = 4;
constexpr int SEQ_T = 2048;
constexpr int N_P   = 16;
constexpr int JD    = 256;
constexpr int NH    = 4;
constexpr int DH    = 16;
constexpr int MEMD  = 64;
constexpr int KOUT  = 192;
constexpr int NSEQ  = N_B * N_P;        // 64
constexpr int NT    = NSEQ * SEQ_T;     // 131072 tokens
constexpr int NPAD  = 256;              // padded projection width (200 -> 256)
constexpr float EPS_LN = 1e-5f;

// ---------------- scratch (device globals; allocation-free) ----------------
__device__ float g_wpack[JD * NPAD];                     // [k][n] packed proj weights
__device__ float g_wtr[MEMD * KOUT];                     // out_w transposed [m][k]
__device__ float g_proj[(size_t)NT * NPAD];              // raw projections
__device__ float g_q[(size_t)NSEQ * NH * SEQ_T * DH];
__device__ float g_k[(size_t)NSEQ * NH * SEQ_T * DH];
__device__ float g_v[(size_t)NSEQ * NH * SEQ_T * DH];
__device__ float g_o[(size_t)NSEQ * NH * SEQ_T * DH];
__device__ float g_beta[NSEQ * NH * SEQ_T];
__device__ float g_alpha[NSEQ * NH * SEQ_T];

// ---------------- f32x2 helpers (Blackwell packed fp32) ----------------
__device__ __forceinline__ unsigned long long dup2(float x) {
    unsigned long long r;
    unsigned int xi = __float_as_uint(x);
    asm("mov.b64 %0, {%1, %1};" : "=l"(r) : "r"(xi));
    return r;
}
__device__ __forceinline__ void fma2(unsigned long long& acc, unsigned long long a,
                                     unsigned long long b) {
    asm("fma.rn.f32x2 %0, %1, %2, %0;" : "+l"(acc) : "l"(a), "l"(b));
}
__device__ __forceinline__ float lo32(unsigned long long v) {
    return __uint_as_float((unsigned int)(v & 0xffffffffull));
}
__device__ __forceinline__ float hi32(unsigned long long v) {
    return __uint_as_float((unsigned int)(v >> 32));
}

__device__ __forceinline__ float sigm(float x) { return 1.0f / (1.0f + expf(-x)); }

// ---------------- kernel 0a: pack projection weights into [k][n] ----------------
__global__ void pack_w(const float* __restrict__ Wq, const float* __restrict__ Wk,
                       const float* __restrict__ Wv, const float* __restrict__ Wbw,
                       const float* __restrict__ Waw) {
    int idx = blockIdx.x * blockDim.x + threadIdx.x;
    if (idx >= JD * NPAD) return;
    int k = idx / NPAD;
    int n = idx % NPAD;
    float val = 0.0f;
    if (n < 64)        val = Wq[n * JD + k];
    else if (n < 128)  val = Wk[(n - 64) * JD + k];
    else if (n < 192)  val = Wv[(n - 128) * JD + k];
    else if (n < 196)  val = Wbw[(n - 192) * JD + k];
    else if (n < 200)  val = Waw[(n - 196) * JD + k];
    g_wpack[idx] = val;
}

// ---------------- kernel 0b: transpose out_w to [m][k] ----------------
__global__ void pack_outw(const float* __restrict__ out_w) {
    int idx = blockIdx.x * blockDim.x + threadIdx.x;
    if (idx >= KOUT * MEMD) return;
    int k = idx / MEMD;
    int m = idx % MEMD;
    g_wtr[m * KOUT + k] = out_w[idx];
}

// ---------------- kernel 1: projection GEMM (NT x 256) @ (256 x 256pad) ----------------
// BM=128, BN=128, BK=16, 256 threads, thread tile 8x8, f32x2 packed FMA.
__global__ __launch_bounds__(256) void gemm_proj(const float* __restrict__ X) {
    __shared__ float As[16][128];
    __shared__ float Bs[16][128];
    int tid = threadIdx.x;
    int m0 = blockIdx.x * 128;
    int n0 = blockIdx.y * 128;
    int tx = tid & 15;
    int ty = tid >> 4;

    unsigned long long acc[8][4];
#pragma unroll
    for (int i = 0; i < 8; i++)
#pragma unroll
        for (int j = 0; j < 4; j++) acc[i][j] = 0ull;

    for (int k0 = 0; k0 < JD; k0 += 16) {
        __syncthreads();
        // stage A (coalesced global, transposed smem store)
#pragma unroll
        for (int r = 0; r < 2; r++) {
            int f = tid + 256 * r;          // [0,512)
            int row = f >> 2;               // [0,128)
            int kq = f & 3;
            float4 v = *(const float4*)(X + (size_t)(m0 + row) * JD + k0 + kq * 4);
            As[kq * 4 + 0][row] = v.x;
            As[kq * 4 + 1][row] = v.y;
            As[kq * 4 + 2][row] = v.z;
            As[kq * 4 + 3][row] = v.w;
        }
        // stage B (contiguous)
#pragma unroll
        for (int r = 0; r < 2; r++) {
            int f = tid + 256 * r;
            int kk = f >> 5;                // [0,16)
            int n4 = f & 31;
            float4 v = *(const float4*)(g_wpack + (size_t)(k0 + kk) * NPAD + n0 + n4 * 4);
            *(float4*)(&Bs[kk][n4 * 4]) = v;
        }
        __syncthreads();
#pragma unroll
        for (int kk = 0; kk < 16; kk++) {
            float4 a0 = *(const float4*)(&As[kk][ty * 8]);
            float4 a1 = *(const float4*)(&As[kk][ty * 8 + 4]);
            const unsigned long long* bp = (const unsigned long long*)(&Bs[kk][tx * 8]);
            unsigned long long b0 = bp[0], b1 = bp[1], b2 = bp[2], b3 = bp[3];
            unsigned long long ad[8];
            ad[0] = dup2(a0.x); ad[1] = dup2(a0.y); ad[2] = dup2(a0.z); ad[3] = dup2(a0.w);
            ad[4] = dup2(a1.x); ad[5] = dup2(a1.y); ad[6] = dup2(a1.z); ad[7] = dup2(a1.w);
#pragma unroll
            for (int i = 0; i < 8; i++) {
                fma2(acc[i][0], ad[i], b0);
                fma2(acc[i][1], ad[i], b1);
                fma2(acc[i][2], ad[i], b2);
                fma2(acc[i][3], ad[i], b3);
            }
        }
    }
    // write back
#pragma unroll
    for (int i = 0; i < 8; i++) {
        float* dst = g_proj + (size_t)(m0 + ty * 8 + i) * NPAD + n0 + tx * 8;
        float4 w0 = make_float4(lo32(acc[i][0]), hi32(acc[i][0]), lo32(acc[i][1]), hi32(acc[i][1]));
        float4 w1 = make_float4(lo32(acc[i][2]), hi32(acc[i][2]), lo32(acc[i][3]), hi32(acc[i][3]));
        *(float4*)(dst) = w0;
        *(float4*)(dst + 4) = w1;
    }
}

// ---------------- kernel 2: epilogue (LN, k-normalize, gates, layout shuffle) --------
__global__ __launch_bounds__(256) void epilogue(const float* __restrict__ curv,
                                                const float* __restrict__ ent,
                                                const float* __restrict__ Wbb,
                                                const float* __restrict__ Wab,
                                                const float* __restrict__ curv_w,
                                                const float* __restrict__ ent_w,
                                                const float* __restrict__ lnqw,
                                                const float* __restrict__ lnqb,
                                                const float* __restrict__ lnkw,
                                                const float* __restrict__ lnkb) {
    int idx = blockIdx.x * 256 + threadIdx.x;   // over NT*NH
    int h = idx & 3;
    int nt = idx >> 2;
    int n = nt >> 11;       // / SEQ_T
    int t = nt & 2047;
    const float* row = g_proj + (size_t)nt * NPAD;

    float qv[16], kv[16], vv[16];
    *(float4*)&qv[0]  = *(const float4*)(row + h * 16 + 0);
    *(float4*)&qv[4]  = *(const float4*)(row + h * 16 + 4);
    *(float4*)&qv[8]  = *(const float4*)(row + h * 16 + 8);
    *(float4*)&qv[12] = *(const float4*)(row + h * 16 + 12);
    *(float4*)&kv[0]  = *(const float4*)(row + 64 + h * 16 + 0);
    *(float4*)&kv[4]  = *(const float4*)(row + 64 + h * 16 + 4);
    *(float4*)&kv[8]  = *(const float4*)(row + 64 + h * 16 + 8);
    *(float4*)&kv[12] = *(const float4*)(row + 64 + h * 16 + 12);
    *(float4*)&vv[0]  = *(const float4*)(row + 128 + h * 16 + 0);
    *(float4*)&vv[4]  = *(const float4*)(row + 128 + h * 16 + 4);
    *(float4*)&vv[8]  = *(const float4*)(row + 128 + h * 16 + 8);
    *(float4*)&vv[12] = *(const float4*)(row + 128 + h * 16 + 12);

    // LN(q)
    float s = 0.0f;
#pragma unroll
    for (int i = 0; i < 16; i++) s += qv[i];
    float mean = s * 0.0625f;
    float var = 0.0f;
#pragma unroll
    for (int i = 0; i < 16; i++) {
        float d = qv[i] - mean;
        var = fmaf(d, d, var);
    }
    var *= 0.0625f;
    float inv = rsqrtf(var + EPS_LN);
#pragma unroll
    for (int i = 0; i < 16; i++) qv[i] = fmaf((qv[i] - mean) * inv, lnqw[i], lnqb[i]);

    // LN(k) then L2-normalize
    s = 0.0f;
#pragma unroll
    for (int i = 0; i < 16; i++) s += kv[i];
    mean = s * 0.0625f;
    var = 0.0f;
#pragma unroll
    for (int i = 0; i < 16; i++) {
        float d = kv[i] - mean;
        var = fmaf(d, d, var);
    }
    var *= 0.0625f;
    inv = rsqrtf(var + EPS_LN);
#pragma unroll
    for (int i = 0; i < 16; i++) kv[i] = fmaf((kv[i] - mean) * inv, lnkw[i], lnkb[i]);
    float nrm = 0.0f;
#pragma unroll
    for (int i = 0; i < 16; i++) nrm = fmaf(kv[i], kv[i], nrm);
    nrm = sqrtf(nrm);
    float rinv = 1.0f / fmaxf(nrm, 1e-12f);
#pragma unroll
    for (int i = 0; i < 16; i++) kv[i] *= rinv;

    // gates (double sigmoid + modulation)
    int b = n / N_P;
    float Kv = fminf(fabsf(curv[b]), 10.0f);
    float Sv = fminf(fmaxf(ent[b], 0.0f), 5.0f);
    float be = sigm(row[192 + h] + Wbb[h]);
    be = sigm(fmaf(Kv, curv_w[h], be));
    float al = sigm(row[196 + h] + Wab[h]);
    al = sigm(fmaf(Sv, ent_w[h], al));

    size_t base = ((size_t)(n * NH + h) * SEQ_T + t) * DH;
    *(float4*)(g_q + base + 0)  = *(float4*)&qv[0];
    *(float4*)(g_q + base + 4)  = *(float4*)&qv[4];
    *(float4*)(g_q + base + 8)  = *(float4*)&qv[8];
    *(float4*)(g_q + base + 12) = *(float4*)&qv[12];
    *(float4*)(g_k + base + 0)  = *(float4*)&kv[0];
    *(float4*)(g_k + base + 4)  = *(float4*)&kv[4];
    *(float4*)(g_k + base + 8)  = *(float4*)&kv[8];
    *(float4*)(g_k + base + 12) = *(float4*)&kv[12];
    *(float4*)(g_v + base + 0)  = *(float4*)&vv[0];
    *(float4*)(g_v + base + 4)  = *(float4*)&vv[4];
    *(float4*)(g_v + base + 8)  = *(float4*)&vv[8];
    *(float4*)(g_v + base + 12) = *(float4*)&vv[12];
    g_beta[(n * NH + h) * SEQ_T + t] = be;
    g_alpha[(n * NH + h) * SEQ_T + t] = al;
}

// ---------------- kernel 3: sequential delta-rule scan ----------------
// One 16-lane group per (n,h) recurrence; 2 recurrences per 32-thread block.
// M (16x16) lives in registers (one row per lane); k/q/v staged to smem in 64-step chunks.
__global__ __launch_bounds__(32) void scan_kernel() {
    __shared__ float sk[2][64][16];
    __shared__ float sv[2][64][16];
    __shared__ float sq[2][64][16];
    __shared__ float sb[2][64];
    __shared__ float sa[2][64];

    int g = threadIdx.x >> 4;
    int lane = threadIdx.x & 15;
    int rec = blockIdx.x * 2 + g;
    size_t base = (size_t)rec * SEQ_T * DH;

    float M[16];
#pragma unroll
    for (int j = 0; j < 16; j++) M[j] = 0.0f;

    for (int c = 0; c < SEQ_T / 64; c++) {
        int t0 = c * 64;
        __syncwarp();
        // stage chunk: 2 recs x 64 steps x 16 floats for k,v,q (+ 64 b,a each)
#pragma unroll
        for (int r = 0; r < 16; r++) {
            int f = threadIdx.x + 32 * r;   // [0,512) float4s
            int gg = f >> 8;
            int e = f & 255;
            size_t src = ((size_t)(blockIdx.x * 2 + gg) * SEQ_T + t0) * DH;
            ((float4*)&sk[gg][0][0])[e] = ((const float4*)(g_k + src))[e];
            ((float4*)&sv[gg][0][0])[e] = ((const float4*)(g_v + src))[e];
            ((float4*)&sq[gg][0][0])[e] = ((const float4*)(g_q + src))[e];
        }
#pragma unroll
        for (int r = 0; r < 4; r++) {
            int f = threadIdx.x + 32 * r;   // [0,128)
            int gg = f >> 6;
            int e = f & 63;
            sb[gg][e] = g_beta[(blockIdx.x * 2 + gg) * SEQ_T + t0 + e];
            sa[gg][e] = g_alpha[(blockIdx.x * 2 + gg) * SEQ_T + t0 + e];
        }
        __syncwarp();

        for (int s = 0; s < 64; s++) {
            float kr[16], qr[16];
            *(float4*)&kr[0]  = *(const float4*)&sk[g][s][0];
            *(float4*)&kr[4]  = *(const float4*)&sk[g][s][4];
            *(float4*)&kr[8]  = *(const float4*)&sk[g][s][8];
            *(float4*)&kr[12] = *(const float4*)&sk[g][s][12];
            *(float4*)&qr[0]  = *(const float4*)&sq[g][s][0];
            *(float4*)&qr[4]  = *(const float4*)&sq[g][s][4];
            *(float4*)&qr[8]  = *(const float4*)&sq[g][s][8];
            *(float4*)&qr[12] = *(const float4*)&sq[g][s][12];
            float vi = sv[g][s][lane];
            float be = sb[g][s];
            float al = sa[g][s];

            // Mk_i (4 parallel partial chains)
            float p0 = M[0] * kr[0], p1 = M[1] * kr[1];
            float p2 = M[2] * kr[2], p3 = M[3] * kr[3];
#pragma unroll
            for (int j = 4; j < 16; j += 4) {
                p0 = fmaf(M[j + 0], kr[j + 0], p0);
                p1 = fmaf(M[j + 1], kr[j + 1], p1);
                p2 = fmaf(M[j + 2], kr[j + 2], p2);
                p3 = fmaf(M[j + 3], kr[j + 3], p3);
            }
            float mk = (p0 + p1) + (p2 + p3);
            float cc = fmaf(be, vi, -al * mk);   // row coefficient

            // M update + output matvec fused
            float o0 = 0.0f, o1 = 0.0f, o2 = 0.0f, o3 = 0.0f;
#pragma unroll
            for (int j = 0; j < 16; j += 4) {
                M[j + 0] = fmaf(cc, kr[j + 0], M[j + 0]); o0 = fmaf(M[j + 0], qr[j + 0], o0);
                M[j + 1] = fmaf(cc, kr[j + 1], M[j + 1]); o1 = fmaf(M[j + 1], qr[j + 1], o1);
                M[j + 2] = fmaf(cc, kr[j + 2], M[j + 2]); o2 = fmaf(M[j + 2], qr[j + 2], o2);
                M[j + 3] = fmaf(cc, kr[j + 3], M[j + 3]); o3 = fmaf(M[j + 3], qr[j + 3], o3);
            }
            g_o[base + (size_t)(t0 + s) * DH + lane] = (o0 + o1) + (o2 + o3);
        }
    }
}

// ---------------- kernel 4: output projection + permuted write ----------------
// block: 192 threads (one per output k), handles one n and 128 t's in 8 tiles of 16.
__global__ __launch_bounds__(192) void final_proj(const float* __restrict__ out_b,
                                                  float* __restrict__ out) {
    __shared__ float so[64][20];   // [m][tt], padded for alignment/banks
    int n = blockIdx.x;
    int tbase = blockIdx.y * 128;
    int kk = threadIdx.x;
    float bias = out_b[kk];
    int b = n >> 4;
    int p = n & 15;

    for (int tile = 0; tile < 8; tile++) {
        int t0 = tbase + tile * 16;
        __syncthreads();
#pragma unroll
        for (int r = 0; r < 6; r++) {
            int e = kk + 192 * r;
            if (e < 1024) {
                int h = e >> 8;
                int tt = (e >> 4) & 15;
                int i = e & 15;
                so[h * 16 + i][tt] =
                    g_o[((size_t)(n * NH + h) * SEQ_T + t0 + tt) * DH + i];
            }
        }
        __syncthreads();

        float acc[16];
#pragma unroll
        for (int tt = 0; tt < 16; tt++) acc[tt] = 0.0f;
#pragma unroll 4
        for (int m = 0; m < 64; m++) {
            float w = g_wtr[m * KOUT + kk];   // L1-resident, coalesced
            float4 o0 = *(const float4*)&so[m][0];
            float4 o1 = *(const float4*)&so[m][4];
            float4 o2 = *(const float4*)&so[m][8];
            float4 o3 = *(const float4*)&so[m][12];
            acc[0]  = fmaf(w, o0.x, acc[0]);  acc[1]  = fmaf(w, o0.y, acc[1]);
            acc[2]  = fmaf(w, o0.z, acc[2]);  acc[3]  = fmaf(w, o0.w, acc[3]);
            acc[4]  = fmaf(w, o1.x, acc[4]);  acc[5]  = fmaf(w, o1.y, acc[5]);
            acc[6]  = fmaf(w, o1.z, acc[6]);  acc[7]  = fmaf(w, o1.w, acc[7]);
            acc[8]  = fmaf(w, o2.x, acc[8]);  acc[9]  = fmaf(w, o2.y, acc[9]);
            acc[10] = fmaf(w, o2.z, acc[10]); acc[11] = fmaf(w, o2.w, acc[11]);
            acc[12] = fmaf(w, o3.x, acc[12]); acc[13] = fmaf(w, o3.y, acc[13]);
            acc[14] = fmaf(w, o3.z, acc[14]); acc[15] = fmaf(w, o3.w, acc[15]);
        }
#pragma unroll
        for (int tt = 0; tt < 16; tt++) {
            out[(((size_t)b * SEQ_T + t0 + tt) * N_P + p) * KOUT + kk] = acc[tt] + bias;
        }
    }
}

// ---------------- launch ----------------
extern "C" void kernel_launch(void* const* d_in, const int* in_sizes, int n_in,
                              void* d_out, int out_size) {
    const float* joint  = (const float*)d_in[0];
    const float* curvat = (const float*)d_in[1];
    const float* entrop = (const float*)d_in[2];
    const float* Wq     = (const float*)d_in[3];
    const float* Wk     = (const float*)d_in[4];
    const float* Wv     = (const float*)d_in[5];
    const float* Wbw    = (const float*)d_in[6];
    const float* Wbb    = (const float*)d_in[7];
    const float* Waw    = (const float*)d_in[8];
    const float* Wab    = (const float*)d_in[9];
    const float* curv_w = (const float*)d_in[10];
    const float* ent_w  = (const float*)d_in[11];
    const float* out_w  = (const float*)d_in[12];
    const float* out_b  = (const float*)d_in[13];
    const float* lnqw   = (const float*)d_in[14];
    const float* lnqb   = (const float*)d_in[15];
    const float* lnkw   = (const float*)d_in[16];
    const float* lnkb   = (const float*)d_in[17];
    float* out = (float*)d_out;

    pack_w<<<(JD * NPAD + 255) / 256, 256>>>(Wq, Wk, Wv, Wbw, Waw);
    pack_outw<<<(KOUT * MEMD + 255) / 256, 256>>>(out_w);
    gemm_proj<<<dim3(NT / 128, NPAD / 128), 256>>>(joint);
    epilogue<<<(NT * NH) / 256, 256>>>(curvat, entrop, Wbb, Wab, curv_w, ent_w,
                                       lnqw, lnqb, lnkw, lnkb);
    scan_kernel<<<(NSEQ * NH) / 2, 32>>>();
    final_proj<<<dim3(NSEQ, SEQ_T / 128), 192>>>(out_b, out);
}